// round 5
// baseline (speedup 1.0000x reference)
#include <cuda_runtime.h>
#include <math.h>

#define NBATCH 4
#define NATOM  512
#define NSYM   4
#define NLAB   16
#define C1     32
#define C2     64
#define NTHR   256
#define GA     2          // atoms per CTA
#define MAXNB  96

__constant__ int c_pf[16] = {0,0,0,0,1,1,1,2,2,3, 0,0,0,0,0,0};
__constant__ int c_ph[16] = {0,1,2,3,1,2,3,2,3,3, 0,0,0,0,0,0};

__global__ __launch_bounds__(NTHR, 6)
void descriptor_kernel(const int*   __restrict__ numbers,
                       const float* __restrict__ coords,
                       const float* __restrict__ nuww0,
                       const float* __restrict__ sigmas0,
                       const float* __restrict__ centres0,
                       const float* __restrict__ nuww1,
                       const float* __restrict__ sigmas1,
                       const float* __restrict__ centres1,
                       float*       __restrict__ out)
{
    __shared__ float4 s_pos[NATOM];                 // 8 KB
    __shared__ float  s_c0s[NLAB * C1];             // 2 KB  centres0*sigma0
    __shared__ float  s_sc1[NLAB * C2];             // 4 KB  centres1*sigma1
    __shared__ float  s_w0[NLAB], s_s0[NLAB], s_w1[NLAB], s_s1[NLAB];
    __shared__ float4 nb_f4[GA][MAXNB];             // 3 KB  (w1*fc, w1*gx, w1*gy, w1*gz)
    __shared__ float2 nb_meta[GA][MAXNB];           // 1.5 KB (rs*s1, laboff bits)
    __shared__ int    s_lab[GA][MAXNB];             // 0.75 KB
    __shared__ float  LmP[GA][2][4][C2];            // 4 KB
    __shared__ float  LmT[GA][4][C2];               // 2 KB
    __shared__ float  s_G[GA][10];
    __shared__ float  s_rf[GA];
    __shared__ int    s_wcnt[GA][4];

    const int tid  = threadIdx.x;
    const int bidx = blockIdx.x;
    const int b    = bidx >> 8;                      // 256 CTAs per batch
    const int li0  = (bidx & 255) * GA;
    const int lane = tid & 31;
    const int g_cmp = tid >> 7;                      // atom served (0/1)
    const int t128  = tid & 127;                     // index within atom group

    // ---- cooperative loads + table pre-scaling ----
    {
        const float* cb  = coords  + (size_t)b * NATOM * 3;
        const int*   nbp = numbers + (size_t)b * NATOM;
        for (int t = tid; t < NATOM; t += NTHR)
            s_pos[t] = make_float4(cb[t * 3 + 0], cb[t * 3 + 1], cb[t * 3 + 2],
                                   __int_as_float(nbp[t]));
        for (int t = tid; t < NLAB * C1; t += NTHR)
            s_c0s[t] = centres0[t] * sigmas0[t >> 5];
        for (int t = tid; t < NLAB * C2; t += NTHR)
            s_sc1[t] = centres1[t] * sigmas1[t >> 6];
        if (tid < NLAB) {
            s_w0[tid] = nuww0[tid];  s_s0[tid] = sigmas0[tid];
            s_w1[tid] = nuww1[tid];  s_s1[tid] = sigmas1[tid];
        }
    }
    __syncthreads();

    // ---- Phase 1a: ballot compaction (4 warps/atom, each covers 128 j) ----
    {
        const int ww = (tid >> 5) & 3;               // quarter within atom
        const int il = li0 + g_cmp;
        const float4 ci = s_pos[il];
        const float xi = ci.x, yi = ci.y, zi = ci.z;

        unsigned mk[4];
        int cnt = 0;
        #pragma unroll
        for (int c = 0; c < 4; c++) {
            const int j = ww * 128 + c * 32 + lane;
            const float4 p = s_pos[j];
            const float dx = p.x - xi, dy = p.y - yi, dz = p.z - zi;
            const float d2 = dx * dx + dy * dy + dz * dz;
            const bool f = (j != il) && (d2 <= 36.0f);
            mk[c] = __ballot_sync(0xffffffffu, f);
            cnt += __popc(mk[c]);
        }
        if (lane == 0) s_wcnt[g_cmp][ww] = cnt;
        __syncthreads();

        int base = 0;
        #pragma unroll
        for (int w = 0; w < 4; w++) if (w < ww) base += s_wcnt[g_cmp][w];
        const unsigned ltmask = (1u << lane) - 1u;
        const int zbase = __float_as_int(ci.w) * NSYM;
        #pragma unroll
        for (int c = 0; c < 4; c++) {
            if ((mk[c] >> lane) & 1u) {
                const int pos = base + __popc(mk[c] & ltmask);
                if (pos < MAXNB) {
                    const int j = ww * 128 + c * 32 + lane;
                    const float4 p = s_pos[j];
                    const float dx = p.x - xi, dy = p.y - yi, dz = p.z - zi;
                    const float d2 = dx * dx + dy * dy + dz * dz;
                    const float rinv = (d2 > 0.0f) ? rsqrtf(d2) : 0.0f;
                    const float d    = d2 * rinv;
                    const float fc   = 0.5f * __cosf(d * 0.52359877559829887f) + 0.5f;
                    const float gg   = rinv * fc;
                    nb_f4[g_cmp][pos] = make_float4(fc, dx * gg, dy * gg, dz * gg);
                    s_lab[g_cmp][pos] = zbase + __float_as_int(p.w);
                }
            }
            base += __popc(mk[c]);
        }
    }
    __syncthreads();

    const int nnb_g = min(s_wcnt[g_cmp][0] + s_wcnt[g_cmp][1] +
                          s_wcnt[g_cmp][2] + s_wcnt[g_cmp][3], MAXNB);

    // ---- Phase 1b: first RConv (8 thr/pair, 16 pairs/sweep/atom) ----
    // All lanes execute shuffles (clamped pc); sub==0 folds w1 into features.
    {
        const int sub  = t128 & 7;
        const int slot = t128 >> 3;                  // 0..15
        const int nIter = (nnb_g + 15) >> 4;         // warp-uniform
        for (int it = 0; it < nIter; it++) {
            const int p  = slot + (it << 4);
            const int pc = (p < nnb_g) ? p : (nnb_g - 1);
            const int   lab = s_lab[g_cmp][pc];
            const float fc  = nb_f4[g_cmp][pc].x;
            const float fcs = fc * s_s0[lab];
            const float4 c4 = *reinterpret_cast<const float4*>(&s_c0s[lab * C1 + sub * 4]);
            const float a0 = fcs - c4.x, a1 = fcs - c4.y, a2 = fcs - c4.z, a3 = fcs - c4.w;
            float sum = __expf(-a0 * a0) + __expf(-a1 * a1)
                      + __expf(-a2 * a2) + __expf(-a3 * a3);
            sum += __shfl_xor_sync(0xffffffffu, sum, 1);
            sum += __shfl_xor_sync(0xffffffffu, sum, 2);
            sum += __shfl_xor_sync(0xffffffffu, sum, 4);
            if (sub == 0 && p < nnb_g) {
                const float rs = s_w0[lab] * sum;
                const float w1 = s_w1[lab];
                nb_meta[g_cmp][p] = make_float2(rs * s_s1[lab],
                                                __int_as_float(lab << 6));
                float4 f = nb_f4[g_cmp][p];
                f.x *= w1; f.y *= w1; f.z *= w1; f.w *= w1;
                nb_f4[g_cmp][p] = f;
            }
        }
    }
    __syncthreads();

    // ---- Phase 2: second RConv + Lm (128 thr/atom: c2 x 2 neighbor slices) ----
    {
        const int c2 = t128 & 63;
        const int sl = t128 >> 6;                    // 0/1
        float a0 = 0.f, a1 = 0.f, a2 = 0.f, a3 = 0.f;
        int k = sl;
        for (; k + 2 < nnb_g; k += 4) {
            const float2 m0 = nb_meta[g_cmp][k];
            const float2 m1 = nb_meta[g_cmp][k + 2];
            const float t0 = m0.x - s_sc1[__float_as_int(m0.y) + c2];
            const float t1 = m1.x - s_sc1[__float_as_int(m1.y) + c2];
            const float p0 = __expf(-t0 * t0);
            const float p1 = __expf(-t1 * t1);
            const float4 f0 = nb_f4[g_cmp][k];
            const float4 f1 = nb_f4[g_cmp][k + 2];
            a0 = fmaf(p0, f0.x, a0); a1 = fmaf(p0, f0.y, a1);
            a2 = fmaf(p0, f0.z, a2); a3 = fmaf(p0, f0.w, a3);
            a0 = fmaf(p1, f1.x, a0); a1 = fmaf(p1, f1.y, a1);
            a2 = fmaf(p1, f1.z, a2); a3 = fmaf(p1, f1.w, a3);
        }
        if (k < nnb_g) {
            const float2 m = nb_meta[g_cmp][k];
            const float t = m.x - s_sc1[__float_as_int(m.y) + c2];
            const float p = __expf(-t * t);
            const float4 f = nb_f4[g_cmp][k];
            a0 = fmaf(p, f.x, a0); a1 = fmaf(p, f.y, a1);
            a2 = fmaf(p, f.z, a2); a3 = fmaf(p, f.w, a3);
        }
        LmP[g_cmp][sl][0][c2] = a0;
        LmP[g_cmp][sl][1][c2] = a1;
        LmP[g_cmp][sl][2][c2] = a2;
        LmP[g_cmp][sl][3][c2] = a3;
    }
    __syncthreads();
    {
        // 128 threads/atom over 256 entries -> 2 each
        #pragma unroll
        for (int r = 0; r < 2; r++) {
            const int e  = t128 + r * 128;
            const int f  = e >> 6;
            const int cc = e & 63;
            LmT[g_cmp][f][cc] = LmP[g_cmp][0][f][cc] + LmP[g_cmp][1][f][cc];
        }
    }
    __syncthreads();

    // ---- Gram G = Lm^T Lm: ALL lanes execute (clamped pc), guarded write ----
    {
        const int p    = t128 >> 2;                  // 0..31
        const int part = t128 & 3;
        const int pc   = (p < 10) ? p : 9;           // clamp: everyone computes
        const int f = c_pf[pc], h = c_ph[pc];
        const float* rowf = LmT[g_cmp][f] + part * 16;
        const float* rowh = LmT[g_cmp][h] + part * 16;
        float sum = 0.0f;
        #pragma unroll
        for (int c = 0; c < 16; c++) sum = fmaf(rowf[c], rowh[c], sum);
        sum += __shfl_xor_sync(0xffffffffu, sum, 1);
        sum += __shfl_xor_sync(0xffffffffu, sum, 2);
        if (part == 0 && p < 10) s_G[g_cmp][p] = sum;
    }
    __syncthreads();
    if (tid < GA) {
        const float* Gp = s_G[tid];
        const float dsum = Gp[0]*Gp[0] + Gp[4]*Gp[4] + Gp[7]*Gp[7] + Gp[9]*Gp[9];
        const float osum = Gp[1]*Gp[1] + Gp[2]*Gp[2] + Gp[3]*Gp[3]
                         + Gp[5]*Gp[5] + Gp[6]*Gp[6] + Gp[8]*Gp[8];
        s_rf[tid] = rsqrtf(dsum + 2.0f * osum);
    }
    __syncthreads();

    // ---- Phase 3: R = Lm Lm^T * rf; barrier-free ----
    const int dd0  = (tid * 4) & 63;
    const int crow = tid >> 4;                       // 0..15
    #pragma unroll
    for (int g = 0; g < GA; g++) {
        const float rf = s_rf[g];
        float4 b0 = *reinterpret_cast<const float4*>(&LmT[g][0][dd0]);
        float4 b1 = *reinterpret_cast<const float4*>(&LmT[g][1][dd0]);
        float4 b2 = *reinterpret_cast<const float4*>(&LmT[g][2][dd0]);
        float4 b3 = *reinterpret_cast<const float4*>(&LmT[g][3][dd0]);
        b0.x *= rf; b0.y *= rf; b0.z *= rf; b0.w *= rf;
        b1.x *= rf; b1.y *= rf; b1.z *= rf; b1.w *= rf;
        b2.x *= rf; b2.y *= rf; b2.z *= rf; b2.w *= rf;
        b3.x *= rf; b3.y *= rf; b3.z *= rf; b3.w *= rf;
        float* ob = out + ((size_t)(bidx * GA + g) << 12);
        #pragma unroll
        for (int grp = 0; grp < 4; grp++) {
            const int c = grp * 16 + crow;
            const float a0 = LmT[g][0][c], a1 = LmT[g][1][c];
            const float a2 = LmT[g][2][c], a3 = LmT[g][3][c];
            float4 st;
            st.x = fmaf(a3, b3.x, fmaf(a2, b2.x, fmaf(a1, b1.x, a0 * b0.x)));
            st.y = fmaf(a3, b3.y, fmaf(a2, b2.y, fmaf(a1, b1.y, a0 * b0.y)));
            st.z = fmaf(a3, b3.z, fmaf(a2, b2.z, fmaf(a1, b1.z, a0 * b0.z)));
            st.w = fmaf(a3, b3.w, fmaf(a2, b2.w, fmaf(a1, b1.w, a0 * b0.w)));
            *reinterpret_cast<float4*>(ob + (grp << 10) + tid * 4) = st;
        }
    }
}

extern "C" void kernel_launch(void* const* d_in, const int* in_sizes, int n_in,
                              void* d_out, int out_size)
{
    // metadata order: boxs, numbers, coords, nuww0, sigmas0, centres0, nuww1, sigmas1, centres1
    const int*   numbers  = (const int*)  d_in[1];
    const float* coords   = (const float*)d_in[2];
    const float* nuww0    = (const float*)d_in[3];
    const float* sigmas0  = (const float*)d_in[4];
    const float* centres0 = (const float*)d_in[5];
    const float* nuww1    = (const float*)d_in[6];
    const float* sigmas1  = (const float*)d_in[7];
    const float* centres1 = (const float*)d_in[8];
    float* out = (float*)d_out;

    descriptor_kernel<<<(NBATCH * NATOM) / GA, NTHR>>>(
        numbers, coords, nuww0, sigmas0, centres0, nuww1, sigmas1, centres1, out);
}

// round 6
// speedup vs baseline: 1.0984x; 1.0984x over previous
#include <cuda_runtime.h>
#include <math.h>

#define NBATCH 4
#define NATOM  512
#define NSYM   4
#define NLAB   16
#define C1     32
#define C2     64
#define NTHR   256
#define GA     4          // atoms per CTA
#define MAXNB  96
#define C0P    36         // padded centres0 row (floats)
#define C1P    68         // padded centres1 / LmT row (floats)
#define SQK    1.2011224087864498f   // sqrt(log2(e))

__constant__ int c_pf[16] = {0,0,0,0,1,1,1,2,2,3, 0,0,0,0,0,0};
__constant__ int c_ph[16] = {0,1,2,3,1,2,3,2,3,3, 0,0,0,0,0,0};

__device__ __forceinline__ float ex2(float x) {
    float r; asm("ex2.approx.ftz.f32 %0, %1;" : "=f"(r) : "f"(x)); return r;
}

__global__ __launch_bounds__(NTHR)
void descriptor_kernel(const int*   __restrict__ numbers,
                       const float* __restrict__ coords,
                       const float* __restrict__ nuww0,
                       const float* __restrict__ sigmas0,
                       const float* __restrict__ centres0,
                       const float* __restrict__ nuww1,
                       const float* __restrict__ sigmas1,
                       const float* __restrict__ centres1,
                       float*       __restrict__ out)
{
    __shared__ float4 s_pos[NATOM];                  // 8 KB
    __shared__ float  s_c0s[NLAB * C0P];             // 2.25 KB (c0*s0*SQK, padded)
    __shared__ float  s_sc1[NLAB * C1P];             // 4.25 KB (c1*s1*SQK, padded)
    __shared__ float  s_w0[NLAB], s_s0f[NLAB], s_w1[NLAB], s_s1f[NLAB];
    __shared__ float4 nb_f4[GA][MAXNB];              // 6 KB   (fc,gx,gy,gz)->(w1*..)
    __shared__ float2 nb_meta[GA][MAXNB];            // 3 KB   (rs*s1*SQK, row offset)
    __shared__ int    s_lab[GA][MAXNB];              // 1.5 KB
    __shared__ float  LmT [GA][4][C1P];              // 4.25 KB
    __shared__ float  LmTs[GA][4][C1P];              // 4.25 KB (rf-scaled copy)
    __shared__ float  s_G[GA][10];
    __shared__ float  s_rf[GA];
    __shared__ int    s_wcnt[GA][2];

    const int tid  = threadIdx.x;
    const int bidx = blockIdx.x;
    const int b    = bidx >> 7;                      // 128 CTAs per batch
    const int li0  = (bidx & 127) * GA;
    const int lane = tid & 31;
    const int g    = tid >> 6;                       // atom served (0..3)
    const int t64  = tid & 63;

    // ---- cooperative loads + folded table pre-scaling ----
    {
        const float* cb  = coords  + (size_t)b * NATOM * 3;
        const int*   nbp = numbers + (size_t)b * NATOM;
        for (int t = tid; t < NATOM; t += NTHR)
            s_pos[t] = make_float4(cb[t * 3 + 0], cb[t * 3 + 1], cb[t * 3 + 2],
                                   __int_as_float(nbp[t]));
        for (int t = tid; t < NLAB * C1; t += NTHR) {
            const int lab = t >> 5, c = t & 31;
            s_c0s[lab * C0P + c] = centres0[t] * sigmas0[lab] * SQK;
        }
        for (int t = tid; t < NLAB * C2; t += NTHR) {
            const int lab = t >> 6, c = t & 63;
            s_sc1[lab * C1P + c] = centres1[t] * sigmas1[lab] * SQK;
        }
        if (tid < NLAB) {
            s_w0[tid]  = nuww0[tid];  s_s0f[tid] = sigmas0[tid] * SQK;
            s_w1[tid]  = nuww1[tid];  s_s1f[tid] = sigmas1[tid] * SQK;
        }
    }
    __syncthreads();

    // ---- Phase 1a: ballot compaction (2 warps/atom, 8 chunks each) ----
    {
        const int ww = (tid >> 5) & 1;
        const int il = li0 + g;
        const float4 ci = s_pos[il];
        const float xi = ci.x, yi = ci.y, zi = ci.z;

        unsigned mk[8];
        int cnt = 0;
        #pragma unroll
        for (int c = 0; c < 8; c++) {
            const int j = ww * 256 + c * 32 + lane;
            const float4 p = s_pos[j];
            const float dx = p.x - xi, dy = p.y - yi, dz = p.z - zi;
            const float d2 = dx * dx + dy * dy + dz * dz;
            const bool f = (j != il) && (d2 <= 36.0f);
            mk[c] = __ballot_sync(0xffffffffu, f);
            cnt += __popc(mk[c]);
        }
        if (lane == 0) s_wcnt[g][ww] = cnt;
        __syncthreads();

        int base = (ww == 1) ? s_wcnt[g][0] : 0;
        const unsigned ltmask = (1u << lane) - 1u;
        const int zbase = __float_as_int(ci.w) * NSYM;
        #pragma unroll
        for (int c = 0; c < 8; c++) {
            if ((mk[c] >> lane) & 1u) {
                const int pos = base + __popc(mk[c] & ltmask);
                if (pos < MAXNB) {
                    const int j = ww * 256 + c * 32 + lane;
                    const float4 p = s_pos[j];
                    const float dx = p.x - xi, dy = p.y - yi, dz = p.z - zi;
                    const float d2 = dx * dx + dy * dy + dz * dz;
                    const float rinv = (d2 > 0.0f) ? rsqrtf(d2) : 0.0f;
                    const float d    = d2 * rinv;
                    const float fc   = 0.5f * __cosf(d * 0.52359877559829887f) + 0.5f;
                    const float gg   = rinv * fc;
                    nb_f4[g][pos] = make_float4(fc, dx * gg, dy * gg, dz * gg);
                    s_lab[g][pos] = zbase + __float_as_int(p.w);
                }
            }
            base += __popc(mk[c]);
        }
    }
    __syncthreads();

    const int nnb = min(s_wcnt[g][0] + s_wcnt[g][1], MAXNB);

    // ---- Phase 1b: first RConv (8 thr/pair, 8 pairs/sweep/atom) ----
    {
        const int sub  = t64 & 7;
        const int slot = t64 >> 3;                   // 0..7
        const int nIter = (nnb + 7) >> 3;            // warp-uniform
        for (int it = 0; it < nIter; it++) {
            const int p  = slot + (it << 3);
            const int pc = (p < nnb) ? p : (nnb - 1);
            const int   lab = s_lab[g][pc];
            const float fc  = nb_f4[g][pc].x;
            const float fcs = fc * s_s0f[lab];
            const float4 c4 = *reinterpret_cast<const float4*>(&s_c0s[lab * C0P + sub * 4]);
            const float a0 = fcs - c4.x, a1 = fcs - c4.y, a2 = fcs - c4.z, a3 = fcs - c4.w;
            float sum = ex2(-a0 * a0) + ex2(-a1 * a1) + ex2(-a2 * a2) + ex2(-a3 * a3);
            sum += __shfl_xor_sync(0xffffffffu, sum, 1);
            sum += __shfl_xor_sync(0xffffffffu, sum, 2);
            sum += __shfl_xor_sync(0xffffffffu, sum, 4);
            if (sub == 0 && p < nnb) {
                const float rs = s_w0[lab] * sum;
                const float w1 = s_w1[lab];
                nb_meta[g][p] = make_float2(rs * s_s1f[lab],
                                            __int_as_float(lab * C1P));
                float4 f = nb_f4[g][p];
                f.x *= w1; f.y *= w1; f.z *= w1; f.w *= w1;
                nb_f4[g][p] = f;
            }
        }
    }
    __syncthreads();

    // ---- Phase 2: second RConv + Lm. 4 c2 x 4 neighbor-slices per thread ----
    {
        const int lw    = t64 >> 5;                  // warp within atom (0/1)
        const int l5    = t64 & 31;
        const int grp   = l5 >> 2;                   // 0..7
        const int slice = l5 & 3;                    // 0..3
        const int c2b   = (lw * 8 + grp) * 4;        // 0..60 step 4

        float acc[4][4];                             // [c2i][f]
        #pragma unroll
        for (int a = 0; a < 4; a++)
            #pragma unroll
            for (int f = 0; f < 4; f++) acc[a][f] = 0.0f;

        for (int k = slice; k < nnb; k += 4) {
            const float2 m = nb_meta[g][k];
            const float4 cc = *reinterpret_cast<const float4*>(
                &s_sc1[__float_as_int(m.y) + c2b]);
            const float t0 = m.x - cc.x, t1 = m.x - cc.y;
            const float t2 = m.x - cc.z, t3 = m.x - cc.w;
            const float p0 = ex2(-t0 * t0), p1 = ex2(-t1 * t1);
            const float p2 = ex2(-t2 * t2), p3 = ex2(-t3 * t3);
            const float4 f = nb_f4[g][k];
            acc[0][0] = fmaf(p0, f.x, acc[0][0]); acc[0][1] = fmaf(p0, f.y, acc[0][1]);
            acc[0][2] = fmaf(p0, f.z, acc[0][2]); acc[0][3] = fmaf(p0, f.w, acc[0][3]);
            acc[1][0] = fmaf(p1, f.x, acc[1][0]); acc[1][1] = fmaf(p1, f.y, acc[1][1]);
            acc[1][2] = fmaf(p1, f.z, acc[1][2]); acc[1][3] = fmaf(p1, f.w, acc[1][3]);
            acc[2][0] = fmaf(p2, f.x, acc[2][0]); acc[2][1] = fmaf(p2, f.y, acc[2][1]);
            acc[2][2] = fmaf(p2, f.z, acc[2][2]); acc[2][3] = fmaf(p2, f.w, acc[2][3]);
            acc[3][0] = fmaf(p3, f.x, acc[3][0]); acc[3][1] = fmaf(p3, f.y, acc[3][1]);
            acc[3][2] = fmaf(p3, f.z, acc[3][2]); acc[3][3] = fmaf(p3, f.w, acc[3][3]);
        }
        // reduce across the 4 slices (lanes xor 1, 2)
        #pragma unroll
        for (int a = 0; a < 4; a++)
            #pragma unroll
            for (int f = 0; f < 4; f++) {
                float v = acc[a][f];
                v += __shfl_xor_sync(0xffffffffu, v, 1);
                v += __shfl_xor_sync(0xffffffffu, v, 2);
                acc[a][f] = v;
            }
        if (slice == 0) {
            #pragma unroll
            for (int f = 0; f < 4; f++)
                *reinterpret_cast<float4*>(&LmT[g][f][c2b]) =
                    make_float4(acc[0][f], acc[1][f], acc[2][f], acc[3][f]);
        }
    }
    __syncthreads();

    // ---- Gram G = Lm^T Lm (10 pairs x 4 parts; clamped, all lanes shuffle) ----
    {
        const int p    = t64 >> 2;                   // 0..15
        const int part = t64 & 3;
        const int pc   = (p < 10) ? p : 9;
        const int f = c_pf[pc], h = c_ph[pc];
        const float4* rf4 = reinterpret_cast<const float4*>(&LmT[g][f][part * 16]);
        const float4* rh4 = reinterpret_cast<const float4*>(&LmT[g][h][part * 16]);
        float sum = 0.0f;
        #pragma unroll
        for (int q = 0; q < 4; q++) {
            const float4 x = rf4[q], y = rh4[q];
            sum = fmaf(x.x, y.x, sum); sum = fmaf(x.y, y.y, sum);
            sum = fmaf(x.z, y.z, sum); sum = fmaf(x.w, y.w, sum);
        }
        sum += __shfl_xor_sync(0xffffffffu, sum, 1);
        sum += __shfl_xor_sync(0xffffffffu, sum, 2);
        if (part == 0 && p < 10) s_G[g][p] = sum;
    }
    __syncthreads();
    if (tid < GA) {
        const float* Gp = s_G[tid];
        const float dsum = Gp[0]*Gp[0] + Gp[4]*Gp[4] + Gp[7]*Gp[7] + Gp[9]*Gp[9];
        const float osum = Gp[1]*Gp[1] + Gp[2]*Gp[2] + Gp[3]*Gp[3]
                         + Gp[5]*Gp[5] + Gp[6]*Gp[6] + Gp[8]*Gp[8];
        s_rf[tid] = rsqrtf(dsum + 2.0f * osum);
    }
    __syncthreads();

    // ---- build rf-scaled copy (one side of the outer product) ----
    #pragma unroll
    for (int r = 0; r < 4; r++) {
        const int idx = tid + r * 256;
        const int gg = idx >> 8, ff = (idx >> 6) & 3, cc = idx & 63;
        LmTs[gg][ff][cc] = LmT[gg][ff][cc] * s_rf[gg];
    }
    __syncthreads();

    // ---- Phase 3: R = Lm (rf*Lm)^T; barrier-free stores ----
    const int dd0  = (tid * 4) & 63;
    const int crow = tid >> 4;                       // 0..15
    #pragma unroll
    for (int g2 = 0; g2 < GA; g2++) {
        const float4 b0 = *reinterpret_cast<const float4*>(&LmTs[g2][0][dd0]);
        const float4 b1 = *reinterpret_cast<const float4*>(&LmTs[g2][1][dd0]);
        const float4 b2 = *reinterpret_cast<const float4*>(&LmTs[g2][2][dd0]);
        const float4 b3 = *reinterpret_cast<const float4*>(&LmTs[g2][3][dd0]);
        float* ob = out + ((size_t)(bidx * GA + g2) << 12);
        #pragma unroll
        for (int grp = 0; grp < 4; grp++) {
            const int c = grp * 16 + crow;
            const float a0 = LmT[g2][0][c], a1 = LmT[g2][1][c];
            const float a2 = LmT[g2][2][c], a3 = LmT[g2][3][c];
            float4 st;
            st.x = fmaf(a3, b3.x, fmaf(a2, b2.x, fmaf(a1, b1.x, a0 * b0.x)));
            st.y = fmaf(a3, b3.y, fmaf(a2, b2.y, fmaf(a1, b1.y, a0 * b0.y)));
            st.z = fmaf(a3, b3.z, fmaf(a2, b2.z, fmaf(a1, b1.z, a0 * b0.z)));
            st.w = fmaf(a3, b3.w, fmaf(a2, b2.w, fmaf(a1, b1.w, a0 * b0.w)));
            *reinterpret_cast<float4*>(ob + (grp << 10) + tid * 4) = st;
        }
    }
}

extern "C" void kernel_launch(void* const* d_in, const int* in_sizes, int n_in,
                              void* d_out, int out_size)
{
    // metadata order: boxs, numbers, coords, nuww0, sigmas0, centres0, nuww1, sigmas1, centres1
    const int*   numbers  = (const int*)  d_in[1];
    const float* coords   = (const float*)d_in[2];
    const float* nuww0    = (const float*)d_in[3];
    const float* sigmas0  = (const float*)d_in[4];
    const float* centres0 = (const float*)d_in[5];
    const float* nuww1    = (const float*)d_in[6];
    const float* sigmas1  = (const float*)d_in[7];
    const float* centres1 = (const float*)d_in[8];
    float* out = (float*)d_out;

    descriptor_kernel<<<(NBATCH * NATOM) / GA, NTHR>>>(
        numbers, coords, nuww0, sigmas0, centres0, nuww1, sigmas1, centres1, out);
}